// round 1
// baseline (speedup 1.0000x reference)
#include <cuda_runtime.h>
#include <math.h>
#include <stdint.h>

#define BATCH   8
#define SEQLEN  2048
#define DMODEL  1024
#define HALF    1024
#define DINNER  2048
#define DSTATE  16
#define DTRANK  64
#define XDBL    96          // DTRANK + 2*DSTATE
#define NTOK    (BATCH*SEQLEN)   // 16384

// ---------------- scratch (static device globals: allocation-guard safe) ----
static __device__ float g_xz   [(size_t)NTOK * DINNER];  // xz = x @ W_in
static __device__ float g_xh   [(size_t)NTOK * HALF];    // silu(conv(xh))
static __device__ float g_delta[(size_t)NTOK * HALF];    // softplus(dt)
static __device__ float g_xdbl [(size_t)NTOK * XDBL];    // [dt_r | B | C]
static __device__ float g_ycat [(size_t)NTOK * DINNER];  // [y | silu(conv(z))]
static __device__ float g_A    [HALF * DSTATE];          // -exp(A_log)

// ---------------- helpers ---------------------------------------------------
__device__ __forceinline__ float siluf(float v) {
    return v / (1.0f + __expf(-v));
}

// ---------------- A = -exp(A_log) -------------------------------------------
__global__ void aprep_k(const float* __restrict__ A_log) {
    int i = blockIdx.x * blockDim.x + threadIdx.x;
    if (i < HALF * DSTATE) g_A[i] = -__expf(A_log[i]);
}

// ---------------- 128x128x16 register-blocked SGEMM -------------------------
// C[M,N] = A[M,K] @ B[K,N] (+ bias). M%128==0, N%128==0, K%16==0 assumed.
__device__ __forceinline__ void sgemm_body(
    const float* __restrict__ A, const float* __restrict__ B,
    const float* __restrict__ bias, float* __restrict__ C,
    int M, int N, int K)
{
    const int BK = 16;
    __shared__ float As[BK * 132];   // [k][m], padded stride 132 (16B aligned)
    __shared__ float Bs[BK * 128];   // [k][n]

    int tid = threadIdx.x;
    int bm = blockIdx.y * 128;
    int bn = blockIdx.x * 128;
    int tx = tid & 15;       // col group (8 cols each)
    int ty = tid >> 4;       // row group (8 rows each)

    float acc[8][8];
#pragma unroll
    for (int i = 0; i < 8; i++)
#pragma unroll
        for (int j = 0; j < 8; j++) acc[i][j] = 0.0f;

    int a_row = tid >> 2;           // 0..63
    int a_col = (tid & 3) << 2;     // 0,4,8,12
    int b_row = tid >> 5;           // 0..7
    int b_col = (tid & 31) << 2;    // 0..124

    const float* Aptr = A + (size_t)bm * K;
    const float* Bptr = B + bn;

    for (int k0 = 0; k0 < K; k0 += BK) {
#pragma unroll
        for (int r = 0; r < 2; r++) {
            int row = a_row + r * 64;
            float4 v = *(const float4*)(Aptr + (size_t)row * K + k0 + a_col);
            As[(a_col + 0) * 132 + row] = v.x;
            As[(a_col + 1) * 132 + row] = v.y;
            As[(a_col + 2) * 132 + row] = v.z;
            As[(a_col + 3) * 132 + row] = v.w;
        }
#pragma unroll
        for (int r = 0; r < 2; r++) {
            int row = b_row + r * 8;
            *(float4*)(&Bs[row * 128 + b_col]) =
                *(const float4*)(Bptr + (size_t)(k0 + row) * N + b_col);
        }
        __syncthreads();

#pragma unroll
        for (int k = 0; k < BK; k++) {
            float4 a0 = *(const float4*)(&As[k * 132 + ty * 8]);
            float4 a1 = *(const float4*)(&As[k * 132 + ty * 8 + 4]);
            float4 b0 = *(const float4*)(&Bs[k * 128 + tx * 8]);
            float4 b1 = *(const float4*)(&Bs[k * 128 + tx * 8 + 4]);
            float af[8] = {a0.x, a0.y, a0.z, a0.w, a1.x, a1.y, a1.z, a1.w};
            float bf[8] = {b0.x, b0.y, b0.z, b0.w, b1.x, b1.y, b1.z, b1.w};
#pragma unroll
            for (int i = 0; i < 8; i++)
#pragma unroll
                for (int j = 0; j < 8; j++)
                    acc[i][j] = fmaf(af[i], bf[j], acc[i][j]);
        }
        __syncthreads();
    }

#pragma unroll
    for (int i = 0; i < 8; i++) {
        int row = bm + ty * 8 + i;
#pragma unroll
        for (int j = 0; j < 8; j += 4) {
            int col = bn + tx * 8 + j;
            float4 v = make_float4(acc[i][j], acc[i][j+1], acc[i][j+2], acc[i][j+3]);
            if (bias) {
                v.x += bias[col];   v.y += bias[col+1];
                v.z += bias[col+2]; v.w += bias[col+3];
            }
            *(float4*)(C + (size_t)row * N + col) = v;
        }
    }
}

__global__ __launch_bounds__(256) void gemm_in_k(
    const float* __restrict__ x, const float* __restrict__ W_in)
{
    sgemm_body(x, W_in, nullptr, g_xz, NTOK, DINNER, DMODEL);
}

__global__ __launch_bounds__(256) void gemm_out_k(
    const float* __restrict__ W_out, const float* __restrict__ b_out,
    float* __restrict__ out)
{
    sgemm_body(g_ycat, W_out, b_out, out, NTOK, DMODEL, DINNER);
}

// ---------------- depthwise conv1d(width 4, SAME: pad_lo=1) + SiLU ----------
// xh = silu(conv(xz[:,:, :HALF], kx)) -> g_xh
// z  = silu(conv(xz[:,:, HALF:], kz)) -> g_ycat[:, HALF:]
__global__ __launch_bounds__(256) void conv_silu_k(
    const float* __restrict__ kx, const float* __restrict__ kz)
{
    int idx = blockIdx.x * 256 + threadIdx.x;       // over NTOK*HALF
    int c  = idx & (HALF - 1);
    int bl = idx >> 10;
    int l  = bl & (SEQLEN - 1);

    float accx = 0.0f, accz = 0.0f;
    const float* base = g_xz + (size_t)bl * DINNER;
#pragma unroll
    for (int w = 0; w < 4; w++) {
        int dl = w - 1;
        int ll = l + dl;
        if (ll >= 0 && ll < SEQLEN) {
            const float* p = base + (ptrdiff_t)dl * DINNER;
            accx = fmaf(p[c],        kx[w * HALF + c], accx);
            accz = fmaf(p[HALF + c], kz[w * HALF + c], accz);
        }
    }
    g_xh  [(size_t)bl * HALF   + c]        = siluf(accx);
    g_ycat[(size_t)bl * DINNER + HALF + c] = siluf(accz);
}

// ---------------- x_dbl = xh @ W_xproj  (M=16384, N=96, K=1024) -------------
__global__ __launch_bounds__(256) void xproj_k(const float* __restrict__ W)
{
    __shared__ float As[32 * 64];   // [k][m]
    __shared__ float Ws[32 * 96];   // [k][n]
    int tid = threadIdx.x;
    int bm = blockIdx.x * 64;
    int tx = tid & 15;   // 6 cols each
    int ty = tid >> 4;   // 4 rows each

    float acc[4][6];
#pragma unroll
    for (int i = 0; i < 4; i++)
#pragma unroll
        for (int j = 0; j < 6; j++) acc[i][j] = 0.0f;

    for (int k0 = 0; k0 < HALF; k0 += 32) {
        for (int i = tid; i < 64 * 32; i += 256) {
            int m = i >> 5, k = i & 31;
            As[k * 64 + m] = g_xh[(size_t)(bm + m) * HALF + k0 + k];
        }
        for (int i = tid; i < 32 * 96; i += 256) {
            int k = i / 96, n = i - k * 96;
            Ws[k * 96 + n] = W[(size_t)(k0 + k) * XDBL + n];
        }
        __syncthreads();
#pragma unroll 8
        for (int k = 0; k < 32; k++) {
            float af[4], wf[6];
#pragma unroll
            for (int i = 0; i < 4; i++) af[i] = As[k * 64 + ty * 4 + i];
#pragma unroll
            for (int j = 0; j < 6; j++) wf[j] = Ws[k * 96 + tx * 6 + j];
#pragma unroll
            for (int i = 0; i < 4; i++)
#pragma unroll
                for (int j = 0; j < 6; j++)
                    acc[i][j] = fmaf(af[i], wf[j], acc[i][j]);
        }
        __syncthreads();
    }
#pragma unroll
    for (int i = 0; i < 4; i++)
#pragma unroll
        for (int j = 0; j < 6; j++)
            g_xdbl[(size_t)(bm + ty * 4 + i) * XDBL + tx * 6 + j] = acc[i][j];
}

// ---------------- delta = softplus(x_dbl[:, :64] @ W_dt + 2*b_dt) -----------
// (reference adds b_dt in dt_proj AND again inside selective_scan)
__global__ __launch_bounds__(256) void dtproj_k(
    const float* __restrict__ Wdt, const float* __restrict__ bdt)
{
    __shared__ float As[64 * 64];   // [k][m]
    __shared__ float Ws[64 * 64];   // [k][n]
    int tid = threadIdx.x;
    int bm = blockIdx.y * 64;
    int bn = blockIdx.x * 64;
    int tx = tid & 15;
    int ty = tid >> 4;

    for (int i = tid; i < 64 * 64; i += 256) {
        int m = i >> 6, k = i & 63;
        As[k * 64 + m] = g_xdbl[(size_t)(bm + m) * XDBL + k];
    }
    for (int i = tid; i < 64 * 64; i += 256) {
        int k = i >> 6, n = i & 63;
        Ws[k * 64 + n] = Wdt[(size_t)k * HALF + bn + n];
    }
    __syncthreads();

    float acc[4][4];
#pragma unroll
    for (int i = 0; i < 4; i++)
#pragma unroll
        for (int j = 0; j < 4; j++) acc[i][j] = 0.0f;

#pragma unroll 16
    for (int k = 0; k < 64; k++) {
        float af[4], wf[4];
#pragma unroll
        for (int i = 0; i < 4; i++) af[i] = As[k * 64 + ty * 4 + i];
#pragma unroll
        for (int j = 0; j < 4; j++) wf[j] = Ws[k * 64 + tx * 4 + j];
#pragma unroll
        for (int i = 0; i < 4; i++)
#pragma unroll
            for (int j = 0; j < 4; j++)
                acc[i][j] = fmaf(af[i], wf[j], acc[i][j]);
    }

#pragma unroll
    for (int i = 0; i < 4; i++) {
        int row = bm + ty * 4 + i;
#pragma unroll
        for (int j = 0; j < 4; j++) {
            int col = bn + tx * 4 + j;
            float v = acc[i][j] + 2.0f * bdt[col];
            float sp = (v > 25.0f) ? v : log1pf(__expf(v));
            g_delta[(size_t)row * HALF + col] = sp;
        }
    }
}

// ---------------- selective scan ---------------------------------------------
// thread = (b, d, n). h in register; l sequential; y = sum_n(h*C) + u*D.
__global__ __launch_bounds__(256) void scan_k(const float* __restrict__ Dvec)
{
    int n  = threadIdx.x & 15;
    int dd = blockIdx.x * 16 + (threadIdx.x >> 4);
    int b  = blockIdx.y;

    float a  = g_A[dd * DSTATE + n];
    float Dd = Dvec[dd];
    float h  = 0.0f;

    const float* up  = g_xh    + (size_t)b * SEQLEN * HALF  + dd;
    const float* dtp = g_delta + (size_t)b * SEQLEN * HALF  + dd;
    const float* bp  = g_xdbl  + (size_t)b * SEQLEN * XDBL  + DTRANK + n;
    float*       yp  = g_ycat  + (size_t)b * SEQLEN * DINNER + dd;

    for (int l = 0; l < SEQLEN; l++) {
        float u  = up [(size_t)l * HALF];
        float dt = dtp[(size_t)l * HALF];
        float Bv = bp [(size_t)l * XDBL];
        float Cv = bp [(size_t)l * XDBL + DSTATE];

        float dA = __expf(dt * a);
        h = fmaf(dA, h, dt * u * Bv);

        float p = h * Cv;
        p += __shfl_xor_sync(0xffffffffu, p, 8);
        p += __shfl_xor_sync(0xffffffffu, p, 4);
        p += __shfl_xor_sync(0xffffffffu, p, 2);
        p += __shfl_xor_sync(0xffffffffu, p, 1);
        if (n == 0) yp[(size_t)l * DINNER] = fmaf(u, Dd, p);
    }
}

// ---------------- launch ------------------------------------------------------
extern "C" void kernel_launch(void* const* d_in, const int* in_sizes, int n_in,
                              void* d_out, int out_size)
{
    const float* x       = (const float*)d_in[0];
    const float* W_in    = (const float*)d_in[1];
    const float* conv_xk = (const float*)d_in[2];
    const float* conv_zk = (const float*)d_in[3];
    const float* W_xproj = (const float*)d_in[4];
    const float* W_dt    = (const float*)d_in[5];
    const float* b_dt    = (const float*)d_in[6];
    const float* A_log   = (const float*)d_in[7];
    const float* Dvec    = (const float*)d_in[8];
    const float* W_out   = (const float*)d_in[9];
    const float* b_out   = (const float*)d_in[10];
    float* out = (float*)d_out;

    aprep_k<<<(HALF * DSTATE + 255) / 256, 256>>>(A_log);

    // xz = x @ W_in : [16384,1024] @ [1024,2048]
    gemm_in_k<<<dim3(DINNER / 128, NTOK / 128), 256>>>(x, W_in);

    // depthwise conv + silu (both halves)
    conv_silu_k<<<(size_t)NTOK * HALF / 256, 256>>>(conv_xk, conv_zk);

    // x_dbl = xh @ W_xproj
    xproj_k<<<NTOK / 64, 256>>>(W_xproj);

    // delta = softplus(x_dbl[:, :64] @ W_dt + 2*b_dt)
    dtproj_k<<<dim3(HALF / 64, NTOK / 64), 256>>>(W_dt, b_dt);

    // selective scan -> g_ycat[:, :HALF]
    scan_k<<<dim3(HALF / 16, BATCH), 256>>>(Dvec);

    // out = [y|z] @ W_out + b_out
    gemm_out_k<<<dim3(DMODEL / 128, NTOK / 128), 256>>>(W_out, b_out, out);
}

// round 2
// speedup vs baseline: 1.0030x; 1.0030x over previous
#include <cuda_runtime.h>
#include <math.h>
#include <stdint.h>

#define BATCH   8
#define SEQLEN  2048
#define DMODEL  1024
#define HALF    1024
#define DINNER  2048
#define DSTATE  16
#define DTRANK  64
#define XDBL    96          // DTRANK + 2*DSTATE
#define NTOK    (BATCH*SEQLEN)   // 16384

// ---------------- scratch (static device globals: allocation-guard safe) ----
static __device__ float g_xz   [(size_t)NTOK * DINNER];  // xz = x @ W_in
static __device__ float g_xh   [(size_t)NTOK * HALF];    // silu(conv(xh))
static __device__ float g_delta[(size_t)NTOK * HALF];    // softplus(dt)
static __device__ float g_xdbl [(size_t)NTOK * XDBL];    // [dt_r | B | C]
static __device__ float g_ycat [(size_t)NTOK * DINNER];  // [y | silu(conv(z))]
static __device__ float g_A    [HALF * DSTATE];          // -exp(A_log)

// ---------------- helpers ---------------------------------------------------
__device__ __forceinline__ float siluf(float v) {
    return v / (1.0f + __expf(-v));
}

// ---------------- A = -exp(A_log) -------------------------------------------
__global__ void aprep_k(const float* __restrict__ A_log) {
    int i = blockIdx.x * blockDim.x + threadIdx.x;
    if (i < HALF * DSTATE) g_A[i] = -__expf(A_log[i]);
}

// ---------------- 128x128x16 register-blocked SGEMM -------------------------
// C[M,N] = A[M,K] @ B[K,N] (+ bias). M%128==0, N%128==0, K%16==0 assumed.
__device__ __forceinline__ void sgemm_body(
    const float* __restrict__ A, const float* __restrict__ B,
    const float* __restrict__ bias, float* __restrict__ C,
    int M, int N, int K)
{
    const int BK = 16;
    __shared__ float As[BK * 132];   // [k][m], padded stride 132 (16B aligned)
    __shared__ float Bs[BK * 128];   // [k][n]

    int tid = threadIdx.x;
    int bm = blockIdx.y * 128;
    int bn = blockIdx.x * 128;
    int tx = tid & 15;       // col group (8 cols each)
    int ty = tid >> 4;       // row group (8 rows each)

    float acc[8][8];
#pragma unroll
    for (int i = 0; i < 8; i++)
#pragma unroll
        for (int j = 0; j < 8; j++) acc[i][j] = 0.0f;

    int a_row = tid >> 2;           // 0..63
    int a_col = (tid & 3) << 2;     // 0,4,8,12
    int b_row = tid >> 5;           // 0..7
    int b_col = (tid & 31) << 2;    // 0..124

    const float* Aptr = A + (size_t)bm * K;
    const float* Bptr = B + bn;

    for (int k0 = 0; k0 < K; k0 += BK) {
#pragma unroll
        for (int r = 0; r < 2; r++) {
            int row = a_row + r * 64;
            float4 v = *(const float4*)(Aptr + (size_t)row * K + k0 + a_col);
            As[(a_col + 0) * 132 + row] = v.x;
            As[(a_col + 1) * 132 + row] = v.y;
            As[(a_col + 2) * 132 + row] = v.z;
            As[(a_col + 3) * 132 + row] = v.w;
        }
#pragma unroll
        for (int r = 0; r < 2; r++) {
            int row = b_row + r * 8;
            *(float4*)(&Bs[row * 128 + b_col]) =
                *(const float4*)(Bptr + (size_t)(k0 + row) * N + b_col);
        }
        __syncthreads();

#pragma unroll
        for (int k = 0; k < BK; k++) {
            float4 a0 = *(const float4*)(&As[k * 132 + ty * 8]);
            float4 a1 = *(const float4*)(&As[k * 132 + ty * 8 + 4]);
            float4 b0 = *(const float4*)(&Bs[k * 128 + tx * 8]);
            float4 b1 = *(const float4*)(&Bs[k * 128 + tx * 8 + 4]);
            float af[8] = {a0.x, a0.y, a0.z, a0.w, a1.x, a1.y, a1.z, a1.w};
            float bf[8] = {b0.x, b0.y, b0.z, b0.w, b1.x, b1.y, b1.z, b1.w};
#pragma unroll
            for (int i = 0; i < 8; i++)
#pragma unroll
                for (int j = 0; j < 8; j++)
                    acc[i][j] = fmaf(af[i], bf[j], acc[i][j]);
        }
        __syncthreads();
    }

#pragma unroll
    for (int i = 0; i < 8; i++) {
        int row = bm + ty * 8 + i;
#pragma unroll
        for (int j = 0; j < 8; j += 4) {
            int col = bn + tx * 8 + j;
            float4 v = make_float4(acc[i][j], acc[i][j+1], acc[i][j+2], acc[i][j+3]);
            if (bias) {
                v.x += bias[col];   v.y += bias[col+1];
                v.z += bias[col+2]; v.w += bias[col+3];
            }
            *(float4*)(C + (size_t)row * N + col) = v;
        }
    }
}

__global__ __launch_bounds__(256) void gemm_in_k(
    const float* __restrict__ x, const float* __restrict__ W_in)
{
    sgemm_body(x, W_in, nullptr, g_xz, NTOK, DINNER, DMODEL);
}

__global__ __launch_bounds__(256) void gemm_out_k(
    const float* __restrict__ W_out, const float* __restrict__ b_out,
    float* __restrict__ out)
{
    sgemm_body(g_ycat, W_out, b_out, out, NTOK, DMODEL, DINNER);
}

// ---------------- depthwise conv1d(width 4, SAME: pad_lo=1) + SiLU ----------
// xh = silu(conv(xz[:,:, :HALF], kx)) -> g_xh
// z  = silu(conv(xz[:,:, HALF:], kz)) -> g_ycat[:, HALF:]
__global__ __launch_bounds__(256) void conv_silu_k(
    const float* __restrict__ kx, const float* __restrict__ kz)
{
    int idx = blockIdx.x * 256 + threadIdx.x;       // over NTOK*HALF
    int c  = idx & (HALF - 1);
    int bl = idx >> 10;
    int l  = bl & (SEQLEN - 1);

    float accx = 0.0f, accz = 0.0f;
    const float* base = g_xz + (size_t)bl * DINNER;
#pragma unroll
    for (int w = 0; w < 4; w++) {
        int dl = w - 1;
        int ll = l + dl;
        if (ll >= 0 && ll < SEQLEN) {
            const float* p = base + (ptrdiff_t)dl * DINNER;
            accx = fmaf(p[c],        kx[w * HALF + c], accx);
            accz = fmaf(p[HALF + c], kz[w * HALF + c], accz);
        }
    }
    g_xh  [(size_t)bl * HALF   + c]        = siluf(accx);
    g_ycat[(size_t)bl * DINNER + HALF + c] = siluf(accz);
}

// ---------------- x_dbl = xh @ W_xproj  (M=16384, N=96, K=1024) -------------
__global__ __launch_bounds__(256) void xproj_k(const float* __restrict__ W)
{
    __shared__ float As[32 * 64];   // [k][m]
    __shared__ float Ws[32 * 96];   // [k][n]
    int tid = threadIdx.x;
    int bm = blockIdx.x * 64;
    int tx = tid & 15;   // 6 cols each
    int ty = tid >> 4;   // 4 rows each

    float acc[4][6];
#pragma unroll
    for (int i = 0; i < 4; i++)
#pragma unroll
        for (int j = 0; j < 6; j++) acc[i][j] = 0.0f;

    for (int k0 = 0; k0 < HALF; k0 += 32) {
        for (int i = tid; i < 64 * 32; i += 256) {
            int m = i >> 5, k = i & 31;
            As[k * 64 + m] = g_xh[(size_t)(bm + m) * HALF + k0 + k];
        }
        for (int i = tid; i < 32 * 96; i += 256) {
            int k = i / 96, n = i - k * 96;
            Ws[k * 96 + n] = W[(size_t)(k0 + k) * XDBL + n];
        }
        __syncthreads();
#pragma unroll 8
        for (int k = 0; k < 32; k++) {
            float af[4], wf[6];
#pragma unroll
            for (int i = 0; i < 4; i++) af[i] = As[k * 64 + ty * 4 + i];
#pragma unroll
            for (int j = 0; j < 6; j++) wf[j] = Ws[k * 96 + tx * 6 + j];
#pragma unroll
            for (int i = 0; i < 4; i++)
#pragma unroll
                for (int j = 0; j < 6; j++)
                    acc[i][j] = fmaf(af[i], wf[j], acc[i][j]);
        }
        __syncthreads();
    }
#pragma unroll
    for (int i = 0; i < 4; i++)
#pragma unroll
        for (int j = 0; j < 6; j++)
            g_xdbl[(size_t)(bm + ty * 4 + i) * XDBL + tx * 6 + j] = acc[i][j];
}

// ---------------- delta = softplus(x_dbl[:, :64] @ W_dt + 2*b_dt) -----------
// (reference adds b_dt in dt_proj AND again inside selective_scan)
__global__ __launch_bounds__(256) void dtproj_k(
    const float* __restrict__ Wdt, const float* __restrict__ bdt)
{
    __shared__ float As[64 * 64];   // [k][m]
    __shared__ float Ws[64 * 64];   // [k][n]
    int tid = threadIdx.x;
    int bm = blockIdx.y * 64;
    int bn = blockIdx.x * 64;
    int tx = tid & 15;
    int ty = tid >> 4;

    for (int i = tid; i < 64 * 64; i += 256) {
        int m = i >> 6, k = i & 63;
        As[k * 64 + m] = g_xdbl[(size_t)(bm + m) * XDBL + k];
    }
    for (int i = tid; i < 64 * 64; i += 256) {
        int k = i >> 6, n = i & 63;
        Ws[k * 64 + n] = Wdt[(size_t)k * HALF + bn + n];
    }
    __syncthreads();

    float acc[4][4];
#pragma unroll
    for (int i = 0; i < 4; i++)
#pragma unroll
        for (int j = 0; j < 4; j++) acc[i][j] = 0.0f;

#pragma unroll 16
    for (int k = 0; k < 64; k++) {
        float af[4], wf[4];
#pragma unroll
        for (int i = 0; i < 4; i++) af[i] = As[k * 64 + ty * 4 + i];
#pragma unroll
        for (int j = 0; j < 4; j++) wf[j] = Ws[k * 64 + tx * 4 + j];
#pragma unroll
        for (int i = 0; i < 4; i++)
#pragma unroll
            for (int j = 0; j < 4; j++)
                acc[i][j] = fmaf(af[i], wf[j], acc[i][j]);
    }

#pragma unroll
    for (int i = 0; i < 4; i++) {
        int row = bm + ty * 4 + i;
#pragma unroll
        for (int j = 0; j < 4; j++) {
            int col = bn + tx * 4 + j;
            float v = acc[i][j] + 2.0f * bdt[col];
            float sp = (v > 25.0f) ? v : log1pf(__expf(v));
            g_delta[(size_t)row * HALF + col] = sp;
        }
    }
}

// ---------------- selective scan ---------------------------------------------
// thread = (b, d, n). h in register; l sequential; y = sum_n(h*C) + u*D.
__global__ __launch_bounds__(256) void scan_k(const float* __restrict__ Dvec)
{
    int n  = threadIdx.x & 15;
    int dd = blockIdx.x * 16 + (threadIdx.x >> 4);
    int b  = blockIdx.y;

    float a  = g_A[dd * DSTATE + n];
    float Dd = Dvec[dd];
    float h  = 0.0f;

    const float* up  = g_xh    + (size_t)b * SEQLEN * HALF  + dd;
    const float* dtp = g_delta + (size_t)b * SEQLEN * HALF  + dd;
    const float* bp  = g_xdbl  + (size_t)b * SEQLEN * XDBL  + DTRANK + n;
    float*       yp  = g_ycat  + (size_t)b * SEQLEN * DINNER + dd;

    for (int l = 0; l < SEQLEN; l++) {
        float u  = up [(size_t)l * HALF];
        float dt = dtp[(size_t)l * HALF];
        float Bv = bp [(size_t)l * XDBL];
        float Cv = bp [(size_t)l * XDBL + DSTATE];

        float dA = __expf(dt * a);
        h = fmaf(dA, h, dt * u * Bv);

        float p = h * Cv;
        p += __shfl_xor_sync(0xffffffffu, p, 8);
        p += __shfl_xor_sync(0xffffffffu, p, 4);
        p += __shfl_xor_sync(0xffffffffu, p, 2);
        p += __shfl_xor_sync(0xffffffffu, p, 1);
        if (n == 0) yp[(size_t)l * DINNER] = fmaf(u, Dd, p);
    }
}

// ---------------- launch ------------------------------------------------------
extern "C" void kernel_launch(void* const* d_in, const int* in_sizes, int n_in,
                              void* d_out, int out_size)
{
    const float* x       = (const float*)d_in[0];
    const float* W_in    = (const float*)d_in[1];
    const float* conv_xk = (const float*)d_in[2];
    const float* conv_zk = (const float*)d_in[3];
    const float* W_xproj = (const float*)d_in[4];
    const float* W_dt    = (const float*)d_in[5];
    const float* b_dt    = (const float*)d_in[6];
    const float* A_log   = (const float*)d_in[7];
    const float* Dvec    = (const float*)d_in[8];
    const float* W_out   = (const float*)d_in[9];
    const float* b_out   = (const float*)d_in[10];
    float* out = (float*)d_out;

    aprep_k<<<(HALF * DSTATE + 255) / 256, 256>>>(A_log);

    // xz = x @ W_in : [16384,1024] @ [1024,2048]
    gemm_in_k<<<dim3(DINNER / 128, NTOK / 128), 256>>>(x, W_in);

    // depthwise conv + silu (both halves)
    conv_silu_k<<<(size_t)NTOK * HALF / 256, 256>>>(conv_xk, conv_zk);

    // x_dbl = xh @ W_xproj
    xproj_k<<<NTOK / 64, 256>>>(W_xproj);

    // delta = softplus(x_dbl[:, :64] @ W_dt + 2*b_dt)
    dtproj_k<<<dim3(HALF / 64, NTOK / 64), 256>>>(W_dt, b_dt);

    // selective scan -> g_ycat[:, :HALF]
    scan_k<<<dim3(HALF / 16, BATCH), 256>>>(Dvec);

    // out = [y|z] @ W_out + b_out
    gemm_out_k<<<dim3(DMODEL / 128, NTOK / 128), 256>>>(W_out, b_out, out);
}

// round 7
// speedup vs baseline: 1.0191x; 1.0160x over previous
#include <cuda_runtime.h>
#include <cuda_bf16.h>
#include <math.h>
#include <stdint.h>

#define BATCH   8
#define SEQLEN  2048
#define DMODEL  1024
#define HALF    1024
#define DINNER  2048
#define DSTATE  16
#define DTRANK  64
#define XDBL    96          // DTRANK + 2*DSTATE
#define NTOK    (BATCH*SEQLEN)   // 16384

// ---------------- scratch (static device globals: allocation-guard safe) ----
static __device__ float g_xz   [(size_t)NTOK * DINNER];  // xz = x @ W_in
static __device__ float g_xh   [(size_t)NTOK * HALF];    // silu(conv(xh))
static __device__ float g_delta[(size_t)NTOK * HALF];    // softplus(dt)
static __device__ float g_xdbl [(size_t)NTOK * XDBL];    // [dt_r | B | C]
static __device__ float g_ycat [(size_t)NTOK * DINNER];  // [y | silu(conv(z))]
static __device__ float g_A    [HALF * DSTATE];          // -exp(A_log)

// ---------------- helpers ---------------------------------------------------
__device__ __forceinline__ float siluf(float v) {
    return v / (1.0f + __expf(-v));
}

// packed f32x2 ops (base Blackwell; explicit PTX only)
__device__ __forceinline__ unsigned long long pack2(float x, float y) {
    unsigned long long r;
    asm("mov.b64 %0, {%1, %2};" : "=l"(r) : "f"(x), "f"(y));
    return r;
}
__device__ __forceinline__ void fma2(unsigned long long& d,
                                     unsigned long long a, unsigned long long b) {
    asm("fma.rn.f32x2 %0, %1, %2, %0;" : "+l"(d) : "l"(a), "l"(b));
}
__device__ __forceinline__ float2 unpack2(unsigned long long v) {
    float x, y;
    asm("mov.b64 {%0, %1}, %2;" : "=f"(x), "=f"(y) : "l"(v));
    return make_float2(x, y);
}

// ---------------- A = -exp(A_log) -------------------------------------------
__global__ void aprep_k(const float* __restrict__ A_log) {
    int i = blockIdx.x * blockDim.x + threadIdx.x;
    if (i < HALF * DSTATE) g_A[i] = -__expf(A_log[i]);
}

// ---------------- 128x128x16 register-blocked SGEMM (f32x2 math) -------------
// C[M,N] = A[M,K] @ B[K,N] (+ bias). M%128==0, N%128==0, K%16==0 assumed.
__device__ __forceinline__ void sgemm_body(
    const float* __restrict__ A, const float* __restrict__ B,
    const float* __restrict__ bias, float* __restrict__ C,
    int M, int N, int K)
{
    const int BK = 16;
    __shared__ float As[BK * 132];   // [k][m], padded stride 132
    __shared__ float Bs[BK * 128];   // [k][n]

    int tid = threadIdx.x;
    int bm = blockIdx.y * 128;
    int bn = blockIdx.x * 128;
    int tx = tid & 15;       // col group (8 cols each)
    int ty = tid >> 4;       // row group (8 rows each)

    // acc2[i][j] holds C[row i][col 2j, 2j+1] packed as f32x2
    unsigned long long acc2[8][4];
#pragma unroll
    for (int i = 0; i < 8; i++)
#pragma unroll
        for (int j = 0; j < 4; j++) acc2[i][j] = 0ULL;

    int a_row = tid >> 2;           // 0..63
    int a_col = (tid & 3) << 2;     // 0,4,8,12
    int b_row = tid >> 5;           // 0..7
    int b_col = (tid & 31) << 2;    // 0..124

    const float* Aptr = A + (size_t)bm * K;
    const float* Bptr = B + bn;

    for (int k0 = 0; k0 < K; k0 += BK) {
#pragma unroll
        for (int r = 0; r < 2; r++) {
            int row = a_row + r * 64;
            float4 v = *(const float4*)(Aptr + (size_t)row * K + k0 + a_col);
            As[(a_col + 0) * 132 + row] = v.x;
            As[(a_col + 1) * 132 + row] = v.y;
            As[(a_col + 2) * 132 + row] = v.z;
            As[(a_col + 3) * 132 + row] = v.w;
        }
#pragma unroll
        for (int r = 0; r < 2; r++) {
            int row = b_row + r * 8;
            *(float4*)(&Bs[row * 128 + b_col]) =
                *(const float4*)(Bptr + (size_t)(k0 + row) * N + b_col);
        }
        __syncthreads();

#pragma unroll
        for (int k = 0; k < BK; k++) {
            float4 a0 = *(const float4*)(&As[k * 132 + ty * 8]);
            float4 a1 = *(const float4*)(&As[k * 132 + ty * 8 + 4]);
            float4 b0 = *(const float4*)(&Bs[k * 128 + tx * 8]);
            float4 b1 = *(const float4*)(&Bs[k * 128 + tx * 8 + 4]);
            unsigned long long bp[4];
            bp[0] = pack2(b0.x, b0.y);
            bp[1] = pack2(b0.z, b0.w);
            bp[2] = pack2(b1.x, b1.y);
            bp[3] = pack2(b1.z, b1.w);
            float af[8] = {a0.x, a0.y, a0.z, a0.w, a1.x, a1.y, a1.z, a1.w};
#pragma unroll
            for (int i = 0; i < 8; i++) {
                unsigned long long ap = pack2(af[i], af[i]);
                fma2(acc2[i][0], ap, bp[0]);
                fma2(acc2[i][1], ap, bp[1]);
                fma2(acc2[i][2], ap, bp[2]);
                fma2(acc2[i][3], ap, bp[3]);
            }
        }
        __syncthreads();
    }

#pragma unroll
    for (int i = 0; i < 8; i++) {
        int row = bm + ty * 8 + i;
#pragma unroll
        for (int j = 0; j < 2; j++) {           // two float4 stores of 8 cols
            int col = bn + tx * 8 + j * 4;
            float2 p0 = unpack2(acc2[i][j * 2]);
            float2 p1 = unpack2(acc2[i][j * 2 + 1]);
            float4 v = make_float4(p0.x, p0.y, p1.x, p1.y);
            if (bias) {
                v.x += bias[col];   v.y += bias[col+1];
                v.z += bias[col+2]; v.w += bias[col+3];
            }
            *(float4*)(C + (size_t)row * N + col) = v;
        }
    }
}

__global__ __launch_bounds__(256) void gemm_in_k(
    const float* __restrict__ x, const float* __restrict__ W_in)
{
    sgemm_body(x, W_in, nullptr, g_xz, NTOK, DINNER, DMODEL);
}

__global__ __launch_bounds__(256) void gemm_out_k(
    const float* __restrict__ W_out, const float* __restrict__ b_out,
    float* __restrict__ out)
{
    sgemm_body(g_ycat, W_out, b_out, out, NTOK, DMODEL, DINNER);
}

// ---------------- depthwise conv1d(width 4, SAME: pad_lo=1) + SiLU ----------
__global__ __launch_bounds__(256) void conv_silu_k(
    const float* __restrict__ kx, const float* __restrict__ kz)
{
    int idx = blockIdx.x * 256 + threadIdx.x;       // over NTOK*HALF
    int c  = idx & (HALF - 1);
    int bl = idx >> 10;
    int l  = bl & (SEQLEN - 1);

    float accx = 0.0f, accz = 0.0f;
    const float* base = g_xz + (size_t)bl * DINNER;
#pragma unroll
    for (int w = 0; w < 4; w++) {
        int dl = w - 1;
        int ll = l + dl;
        if (ll >= 0 && ll < SEQLEN) {
            const float* p = base + (ptrdiff_t)dl * DINNER;
            accx = fmaf(p[c],        kx[w * HALF + c], accx);
            accz = fmaf(p[HALF + c], kz[w * HALF + c], accz);
        }
    }
    g_xh  [(size_t)bl * HALF   + c]        = siluf(accx);
    g_ycat[(size_t)bl * DINNER + HALF + c] = siluf(accz);
}

// ---------------- x_dbl = xh @ W_xproj  (M=16384, N=96, K=1024) -------------
__global__ __launch_bounds__(256) void xproj_k(const float* __restrict__ W)
{
    __shared__ float As[32 * 64];   // [k][m]
    __shared__ float Ws[32 * 96];   // [k][n]
    int tid = threadIdx.x;
    int bm = blockIdx.x * 64;
    int tx = tid & 15;   // 6 cols each
    int ty = tid >> 4;   // 4 rows each

    float acc[4][6];
#pragma unroll
    for (int i = 0; i < 4; i++)
#pragma unroll
        for (int j = 0; j < 6; j++) acc[i][j] = 0.0f;

    for (int k0 = 0; k0 < HALF; k0 += 32) {
        for (int i = tid; i < 64 * 32; i += 256) {
            int m = i >> 5, k = i & 31;
            As[k * 64 + m] = g_xh[(size_t)(bm + m) * HALF + k0 + k];
        }
        for (int i = tid; i < 32 * 96; i += 256) {
            int k = i / 96, n = i - k * 96;
            Ws[k * 96 + n] = W[(size_t)(k0 + k) * XDBL + n];
        }
        __syncthreads();
#pragma unroll 8
        for (int k = 0; k < 32; k++) {
            float af[4], wf[6];
#pragma unroll
            for (int i = 0; i < 4; i++) af[i] = As[k * 64 + ty * 4 + i];
#pragma unroll
            for (int j = 0; j < 6; j++) wf[j] = Ws[k * 96 + tx * 6 + j];
#pragma unroll
            for (int i = 0; i < 4; i++)
#pragma unroll
                for (int j = 0; j < 6; j++)
                    acc[i][j] = fmaf(af[i], wf[j], acc[i][j]);
        }
        __syncthreads();
    }
#pragma unroll
    for (int i = 0; i < 4; i++)
#pragma unroll
        for (int j = 0; j < 6; j++)
            g_xdbl[(size_t)(bm + ty * 4 + i) * XDBL + tx * 6 + j] = acc[i][j];
}

// ---------------- delta = softplus(x_dbl[:, :64] @ W_dt + 2*b_dt) -----------
// (reference adds b_dt in dt_proj AND again inside selective_scan)
__global__ __launch_bounds__(256) void dtproj_k(
    const float* __restrict__ Wdt, const float* __restrict__ bdt)
{
    __shared__ float As[64 * 64];   // [k][m]
    __shared__ float Ws[64 * 64];   // [k][n]
    int tid = threadIdx.x;
    int bm = blockIdx.y * 64;
    int bn = blockIdx.x * 64;
    int tx = tid & 15;
    int ty = tid >> 4;

    for (int i = tid; i < 64 * 64; i += 256) {
        int m = i >> 6, k = i & 63;
        As[k * 64 + m] = g_xdbl[(size_t)(bm + m) * XDBL + k];
    }
    for (int i = tid; i < 64 * 64; i += 256) {
        int k = i >> 6, n = i & 63;
        Ws[k * 64 + n] = Wdt[(size_t)k * HALF + bn + n];
    }
    __syncthreads();

    float acc[4][4];
#pragma unroll
    for (int i = 0; i < 4; i++)
#pragma unroll
        for (int j = 0; j < 4; j++) acc[i][j] = 0.0f;

#pragma unroll 16
    for (int k = 0; k < 64; k++) {
        float af[4], wf[4];
#pragma unroll
        for (int i = 0; i < 4; i++) af[i] = As[k * 64 + ty * 4 + i];
#pragma unroll
        for (int j = 0; j < 4; j++) wf[j] = Ws[k * 64 + tx * 4 + j];
#pragma unroll
        for (int i = 0; i < 4; i++)
#pragma unroll
            for (int j = 0; j < 4; j++)
                acc[i][j] = fmaf(af[i], wf[j], acc[i][j]);
    }

#pragma unroll
    for (int i = 0; i < 4; i++) {
        int row = bm + ty * 4 + i;
#pragma unroll
        for (int j = 0; j < 4; j++) {
            int col = bn + tx * 4 + j;
            float v = acc[i][j] + 2.0f * bdt[col];
            float sp = (v > 25.0f) ? v : log1pf(__expf(v));
            g_delta[(size_t)row * HALF + col] = sp;
        }
    }
}

// ---------------- selective scan ---------------------------------------------
// thread = (b, d, n). h in register; l sequential; y = sum_n(h*C) + u*D.
__global__ __launch_bounds__(256) void scan_k(const float* __restrict__ Dvec)
{
    int n  = threadIdx.x & 15;
    int dd = blockIdx.x * 16 + (threadIdx.x >> 4);
    int b  = blockIdx.y;

    float a  = g_A[dd * DSTATE + n];
    float Dd = Dvec[dd];
    float h  = 0.0f;

    const float* up  = g_xh    + (size_t)b * SEQLEN * HALF  + dd;
    const float* dtp = g_delta + (size_t)b * SEQLEN * HALF  + dd;
    const float* bp  = g_xdbl  + (size_t)b * SEQLEN * XDBL  + DTRANK + n;
    float*       yp  = g_ycat  + (size_t)b * SEQLEN * DINNER + dd;

    for (int l = 0; l < SEQLEN; l++) {
        float u  = up [(size_t)l * HALF];
        float dt = dtp[(size_t)l * HALF];
        float Bv = bp [(size_t)l * XDBL];
        float Cv = bp [(size_t)l * XDBL + DSTATE];

        float dA = __expf(dt * a);
        h = fmaf(dA, h, dt * u * Bv);

        float p = h * Cv;
        p += __shfl_xor_sync(0xffffffffu, p, 8);
        p += __shfl_xor_sync(0xffffffffu, p, 4);
        p += __shfl_xor_sync(0xffffffffu, p, 2);
        p += __shfl_xor_sync(0xffffffffu, p, 1);
        if (n == 0) yp[(size_t)l * DINNER] = fmaf(u, Dd, p);
    }
}

// ---------------- launch ------------------------------------------------------
extern "C" void kernel_launch(void* const* d_in, const int* in_sizes, int n_in,
                              void* d_out, int out_size)
{
    const float* x       = (const float*)d_in[0];
    const float* W_in    = (const float*)d_in[1];
    const float* conv_xk = (const float*)d_in[2];
    const float* conv_zk = (const float*)d_in[3];
    const float* W_xproj = (const float*)d_in[4];
    const float* W_dt    = (const float*)d_in[5];
    const float* b_dt    = (const float*)d_in[6];
    const float* A_log   = (const float*)d_in[7];
    const float* Dvec    = (const float*)d_in[8];
    const float* W_out   = (const float*)d_in[9];
    const float* b_out   = (const float*)d_in[10];
    float* out = (float*)d_out;

    aprep_k<<<(HALF * DSTATE + 255) / 256, 256>>>(A_log);

    // xz = x @ W_in : [16384,1024] @ [1024,2048]
    gemm_in_k<<<dim3(DINNER / 128, NTOK / 128), 256>>>(x, W_in);

    // depthwise conv + silu (both halves)
    conv_silu_k<<<(size_t)NTOK * HALF / 256, 256>>>(conv_xk, conv_zk);

    // x_dbl = xh @ W_xproj
    xproj_k<<<NTOK / 64, 256>>>(W_xproj);

    // delta = softplus(x_dbl[:, :64] @ W_dt + 2*b_dt)
    dtproj_k<<<dim3(HALF / 64, NTOK / 64), 256>>>(W_dt, b_dt);

    // selective scan -> g_ycat[:, :HALF]
    scan_k<<<dim3(HALF / 16, BATCH), 256>>>(Dvec);

    // out = [y|z] @ W_out + b_out
    gemm_out_k<<<dim3(DMODEL / 128, NTOK / 128), 256>>>(W_out, b_out, out);
}